// round 2
// baseline (speedup 1.0000x reference)
#include <cuda_runtime.h>
#include <math.h>

#define B_N 8192
#define D_K 256
#define NCLS 64
#define TILE 128
#define KT 16
#define MARGIN 0.5f

// Scratch (no allocations allowed) — re-initialized on every launch.
__device__ unsigned int g_dap[B_N];   // hardest positive distance, float bits
__device__ unsigned int g_dan[B_N];   // closest  negative distance, float bits
__device__ int          g_cnt[NCLS];  // class counts
__device__ float        g_sq[B_N];    // squared row norms

// ---------------------------------------------------------------------------
__global__ void zero_kernel() {
    int i = blockIdx.x * blockDim.x + threadIdx.x;
    if (i < B_N) { g_dap[i] = 0u; g_dan[i] = 0x7F7FFFFFu; /* FLT_MAX bits */ }
    if (i < NCLS) g_cnt[i] = 0;
}

// Row norms (one warp per row) + class counts.
__global__ void prep_kernel(const float* __restrict__ x, const int* __restrict__ lab) {
    int gtid = blockIdx.x * blockDim.x + threadIdx.x;
    int warp = gtid >> 5;
    int lane = threadIdx.x & 31;
    if (warp < B_N) {
        const float4* xr = (const float4*)(x + warp * D_K);
        float s = 0.f;
#pragma unroll
        for (int t = 0; t < 2; t++) {
            float4 v = xr[lane + 32 * t];
            s += v.x * v.x + v.y * v.y + v.z * v.z + v.w * v.w;
        }
#pragma unroll
        for (int o = 16; o; o >>= 1) s += __shfl_xor_sync(0xffffffffu, s, o);
        if (lane == 0) g_sq[warp] = s;
    }
    if (gtid < B_N) atomicAdd(&g_cnt[lab[gtid]], 1);
}

// ---------------------------------------------------------------------------
// Fused tile kernel: 128x128 tile of the Gram matrix + distance epilogue
// with per-row pos-max / neg-min mining.
__global__ void __launch_bounds__(256, 2) tile_kernel(const float* __restrict__ x,
                                                      const int* __restrict__ lab) {
    __shared__ float As[KT][TILE];
    __shared__ float Bs[KT][TILE];
    __shared__ int   labR[TILE], labC[TILE];
    __shared__ float sqR[TILE], sqC[TILE];
    __shared__ unsigned int smax[TILE], smin[TILE];

    const int rowBase = blockIdx.y * TILE;
    const int colBase = blockIdx.x * TILE;
    const int tid = threadIdx.x;
    const int tx = tid & 15;     // 16 col-threads
    const int ty = tid >> 4;     // 16 row-threads

    if (tid < TILE) {
        labR[tid] = lab[rowBase + tid];
        labC[tid] = lab[colBase + tid];
        sqR[tid]  = g_sq[rowBase + tid];
        sqC[tid]  = g_sq[colBase + tid];
        smax[tid] = 0u;
        smin[tid] = 0x7F7FFFFFu;
    }

    float acc[8][8] = {};

    for (int kc = 0; kc < D_K; kc += KT) {
        // Stage a 128x16 slab of each operand. 512 float4 per slab, 2 per thread.
        // r = f & 127 keeps consecutive lanes on consecutive smem rows ->
        // conflict-free STS.
#pragma unroll
        for (int it = 0; it < 2; it++) {
            int f   = tid + it * 256;
            int r   = f & 127;
            int kq  = (f >> 7) << 2;  // 0,4,8,12
            float4 v = *(const float4*)(x + (rowBase + r) * D_K + kc + kq);
            As[kq + 0][r] = v.x; As[kq + 1][r] = v.y;
            As[kq + 2][r] = v.z; As[kq + 3][r] = v.w;
            float4 w = *(const float4*)(x + (colBase + r) * D_K + kc + kq);
            Bs[kq + 0][r] = w.x; Bs[kq + 1][r] = w.y;
            Bs[kq + 2][r] = w.z; Bs[kq + 3][r] = w.w;
        }
        __syncthreads();

#pragma unroll
        for (int kk = 0; kk < KT; kk++) {
            float a[8], b[8];
            *(float4*)&a[0] = *(const float4*)&As[kk][ty * 8];
            *(float4*)&a[4] = *(const float4*)&As[kk][ty * 8 + 4];
            *(float4*)&b[0] = *(const float4*)&Bs[kk][tx * 8];
            *(float4*)&b[4] = *(const float4*)&Bs[kk][tx * 8 + 4];
#pragma unroll
            for (int i = 0; i < 8; i++)
#pragma unroll
                for (int j = 0; j < 8; j++)
                    acc[i][j] = fmaf(a[i], b[j], acc[i][j]);
        }
        __syncthreads();
    }

    // Epilogue: distances + semi-hard mining reductions.
#pragma unroll
    for (int i = 0; i < 8; i++) {
        int r    = ty * 8 + i;
        int grow = rowBase + r;
        int rl   = labR[r];
        float rsq = sqR[r];
        float pmax = -1.0f;
        float nmin = 1e30f;
#pragma unroll
        for (int j = 0; j < 8; j++) {
            int c    = tx * 8 + j;
            int gcol = colBase + c;
            float d2 = rsq + sqC[c] - 2.0f * acc[i][j];
            d2 = fmaxf(d2, 0.0f);
            float d = sqrtf(d2);
            if (rl == labC[c]) {
                if (gcol != grow) pmax = fmaxf(pmax, d);
            } else {
                nmin = fminf(nmin, d);
            }
        }
        // Non-negative floats: bit pattern order == value order.
        if (pmax >= 0.0f)  atomicMax(&smax[r], __float_as_uint(pmax));
        if (nmin < 1e29f)  atomicMin(&smin[r], __float_as_uint(nmin));
    }
    __syncthreads();
    if (tid < TILE) {
        atomicMax(&g_dap[rowBase + tid], smax[tid]);
        atomicMin(&g_dan[rowBase + tid], smin[tid]);
    }
}

// ---------------------------------------------------------------------------
__global__ void final_kernel(const int* __restrict__ lab, float* __restrict__ out) {
    __shared__ float ssum[256];
    __shared__ int   scnt[256];
    int tid = threadIdx.x;
    float tot = 0.f;
    int   cnt = 0;
    for (int i = tid; i < B_N; i += 256) {
        float dap = __uint_as_float(g_dap[i]);
        float dan = __uint_as_float(g_dan[i]);
        int c = g_cnt[lab[i]];
        bool has_pos = (c > 1);
        bool has_neg = (c < B_N);
        float loss = dap - dan + MARGIN;   // >0  <=>  d_an < d_ap + margin
        if (has_pos && has_neg && loss > 0.f) { tot += loss; cnt++; }
    }
    ssum[tid] = tot; scnt[tid] = cnt;
    __syncthreads();
    for (int s = 128; s; s >>= 1) {
        if (tid < s) { ssum[tid] += ssum[tid + s]; scnt[tid] += scnt[tid + s]; }
        __syncthreads();
    }
    if (tid == 0) out[0] = (scnt[0] > 0) ? ssum[0] / (float)scnt[0] : 0.0f;
}

// ---------------------------------------------------------------------------
extern "C" void kernel_launch(void* const* d_in, const int* in_sizes, int n_in,
                              void* d_out, int out_size) {
    const float* emb = (const float*)d_in[0];
    const int*   lab = (const int*)d_in[1];
    float*       out = (float*)d_out;

    zero_kernel<<<(B_N + 255) / 256, 256>>>();
    prep_kernel<<<(B_N * 32) / 256, 256>>>(emb, lab);
    dim3 grid(B_N / TILE, B_N / TILE);
    tile_kernel<<<grid, 256>>>(emb, lab);
    final_kernel<<<1, 256>>>(lab, out);
}

// round 13
// speedup vs baseline: 5.6677x; 5.6677x over previous
#include <cuda_runtime.h>
#include <cuda_bf16.h>
#include <cstdint>

#define B_N 8192
#define D_K 256
#define NCLS 64
#define MARGIN 0.5f
#define TILE 128

// Scratch (allocations are forbidden) — re-initialized every launch.
__device__ unsigned int g_dap[B_N];            // hardest positive d^2, float bits
__device__ unsigned int g_dan[B_N];            // closest  negative d^2, float bits
__device__ int          g_cnt[NCLS];
__device__ float        g_sq[B_N];
__device__ __nv_bfloat16 g_xbf[B_N * D_K];     // bf16 copy of embeddings (4 MB)

// SMEM layout (bytes). Padded row stride 528 B (264 bf16) -> conflict-free
// ldmatrix (row step = 16B in 128B-line space) and STS.
#define A_STRIDE 528
#define SM_A     0
#define SM_B     67584
#define SM_LABC  135168
#define SM_SQC   135680
#define SM_LABR  136192
#define SM_SQR   136704
#define SM_MAX   137216
#define SM_MIN   137728
#define SMEM_BYTES 138240

__device__ __forceinline__ uint32_t smem_u32(const void* p) {
    uint32_t a;
    asm("{ .reg .u64 t; cvta.to.shared.u64 t, %1; cvt.u32.u64 %0, t; }"
        : "=r"(a) : "l"(p));
    return a;
}
__device__ __forceinline__ uint32_t pack_bf16x2(float lo, float hi) {
    __nv_bfloat162 h = __floats2bfloat162_rn(lo, hi);
    return *(uint32_t*)&h;
}

// ---------------------------------------------------------------------------
__global__ void zero_kernel() {
    int i = blockIdx.x * blockDim.x + threadIdx.x;
    if (i < B_N) { g_dap[i] = 0u; g_dan[i] = 0x7F7FFFFFu; }
    if (i < NCLS) g_cnt[i] = 0;
}

// Row norms + class counts + bf16 conversion. One warp per row.
__global__ void prep_kernel(const float* __restrict__ x, const int* __restrict__ lab) {
    int gtid = blockIdx.x * blockDim.x + threadIdx.x;
    int warp = gtid >> 5;
    int lane = threadIdx.x & 31;
    if (warp < B_N) {
        const float4* xr = (const float4*)(x + (size_t)warp * D_K);
        float s = 0.f;
#pragma unroll
        for (int t = 0; t < 2; t++) {
            float4 v = xr[lane + 32 * t];
            s += v.x * v.x + v.y * v.y + v.z * v.z + v.w * v.w;
            *(uint2*)(g_xbf + (size_t)warp * D_K + (lane + 32 * t) * 4) =
                make_uint2(pack_bf16x2(v.x, v.y), pack_bf16x2(v.z, v.w));
        }
#pragma unroll
        for (int o = 16; o; o >>= 1) s += __shfl_xor_sync(0xffffffffu, s, o);
        if (lane == 0) g_sq[warp] = s;
    }
    if (gtid < B_N) atomicAdd(&g_cnt[lab[gtid]], 1);
}

// ---------------------------------------------------------------------------
// 128x128 Gram tile via bf16 mma.sync.m16n8k16 + fused mining on d^2.
// 8 warps: warp (wid&1) -> M half (64), (wid>>1) -> N quarter (32).
__global__ void __launch_bounds__(256, 1)
tile_kernel(const int* __restrict__ lab) {
    extern __shared__ char smem[];
    const uint32_t sb = smem_u32(smem);
    const int tid  = threadIdx.x;
    const int wid  = tid >> 5;
    const int lane = tid & 31;
    const int rowBase = blockIdx.y * TILE;
    const int colBase = blockIdx.x * TILE;

    if (tid < TILE) {
        ((int*)(smem + SM_LABC))[tid]  = lab[colBase + tid];
        ((float*)(smem + SM_SQC))[tid] = g_sq[colBase + tid];
        ((int*)(smem + SM_LABR))[tid]  = lab[rowBase + tid];
        ((float*)(smem + SM_SQR))[tid] = g_sq[rowBase + tid];
        ((uint32_t*)(smem + SM_MAX))[tid] = 0u;
        ((uint32_t*)(smem + SM_MIN))[tid] = 0x7F7FFFFFu;
    }

    // Stage A and B tiles (128 x 256 bf16 each) from the bf16 copy.
    // 4096 uint4 per operand; 16 per thread.
#pragma unroll
    for (int it = 0; it < 16; it++) {
        int idx = tid + it * 256;
        int r = idx >> 5, q = idx & 31;              // q: 16B chunk in row
        uint4 va = *(const uint4*)(g_xbf + (size_t)(rowBase + r) * D_K + q * 8);
        *(uint4*)(smem + SM_A + r * A_STRIDE + q * 16) = va;
        uint4 vb = *(const uint4*)(g_xbf + (size_t)(colBase + r) * D_K + q * 8);
        *(uint4*)(smem + SM_B + r * A_STRIDE + q * 16) = vb;
    }
    __syncthreads();

    const int wm = (wid & 1) * 64;    // warp M offset
    const int wn = (wid >> 1) * 32;   // warp N offset

    float acc[4][4][4];
#pragma unroll
    for (int mf = 0; mf < 4; mf++)
#pragma unroll
        for (int nf = 0; nf < 4; nf++)
#pragma unroll
            for (int e = 0; e < 4; e++) acc[mf][nf][e] = 0.f;

#pragma unroll 4
    for (int ks = 0; ks < 16; ks++) {
        uint32_t a[4][4], b[4][2];
#pragma unroll
        for (int mf = 0; mf < 4; mf++) {
            uint32_t addr = sb + SM_A + (wm + mf * 16 + (lane & 15)) * A_STRIDE
                          + ks * 32 + (lane >> 4) * 16;
            asm volatile("ldmatrix.sync.aligned.m8n8.x4.shared.b16 "
                         "{%0,%1,%2,%3}, [%4];"
                         : "=r"(a[mf][0]), "=r"(a[mf][1]),
                           "=r"(a[mf][2]), "=r"(a[mf][3]) : "r"(addr));
        }
#pragma unroll
        for (int nf = 0; nf < 4; nf++) {
            uint32_t addr = sb + SM_B + (wn + nf * 8 + (lane & 7)) * A_STRIDE
                          + ks * 32 + ((lane >> 3) & 1) * 16;
            asm volatile("ldmatrix.sync.aligned.m8n8.x2.shared.b16 "
                         "{%0,%1}, [%2];"
                         : "=r"(b[nf][0]), "=r"(b[nf][1]) : "r"(addr));
        }
#pragma unroll
        for (int mf = 0; mf < 4; mf++)
#pragma unroll
            for (int nf = 0; nf < 4; nf++)
                asm volatile(
                    "mma.sync.aligned.m16n8k16.row.col.f32.bf16.bf16.f32 "
                    "{%0,%1,%2,%3}, {%4,%5,%6,%7}, {%8,%9}, {%0,%1,%2,%3};"
                    : "+f"(acc[mf][nf][0]), "+f"(acc[mf][nf][1]),
                      "+f"(acc[mf][nf][2]), "+f"(acc[mf][nf][3])
                    : "r"(a[mf][0]), "r"(a[mf][1]), "r"(a[mf][2]), "r"(a[mf][3]),
                      "r"(b[nf][0]), "r"(b[nf][1]));
    }

    // Epilogue: fragment c0,c1 -> row lane/4, cols 2*(lane&3)+{0,1};
    //           c2,c3 -> row+8.  Mine per-row pos-max / neg-min on d^2.
    const int*   labC = (const int*)(smem + SM_LABC);
    const float* sqC  = (const float*)(smem + SM_SQC);
    const int*   labR = (const int*)(smem + SM_LABR);
    const float* sqR  = (const float*)(smem + SM_SQR);
    uint32_t* smax = (uint32_t*)(smem + SM_MAX);
    uint32_t* smin = (uint32_t*)(smem + SM_MIN);

#pragma unroll
    for (int mf = 0; mf < 4; mf++) {
#pragma unroll
        for (int half = 0; half < 2; half++) {
            int r = wm + mf * 16 + (lane >> 2) + half * 8;
            int grow = rowBase + r;
            int rl = labR[r];
            float rsq = sqR[r];
            float pmax = -1.0f, nmin = 1e30f;
#pragma unroll
            for (int nf = 0; nf < 4; nf++)
#pragma unroll
                for (int e = 0; e < 2; e++) {
                    int c = wn + nf * 8 + (lane & 3) * 2 + e;
                    float dot = acc[mf][nf][half * 2 + e];
                    float d2 = fmaxf(rsq + sqC[c] - 2.0f * dot, 0.0f);
                    if (rl == labC[c]) {
                        if (colBase + c != grow) pmax = fmaxf(pmax, d2);
                    } else {
                        nmin = fminf(nmin, d2);
                    }
                }
            if (pmax >= 0.0f) atomicMax(&smax[r], __float_as_uint(pmax));
            if (nmin < 1e29f) atomicMin(&smin[r], __float_as_uint(nmin));
        }
    }
    __syncthreads();
    if (tid < TILE) {
        atomicMax(&g_dap[rowBase + tid], smax[tid]);
        atomicMin(&g_dan[rowBase + tid], smin[tid]);
    }
}

// ---------------------------------------------------------------------------
__global__ void final_kernel(const int* __restrict__ lab, float* __restrict__ out) {
    __shared__ float ssum[1024];
    __shared__ int   scnt[1024];
    int tid = threadIdx.x;
    float tot = 0.f;
    int   cnt = 0;
    for (int i = tid; i < B_N; i += 1024) {
        float dap = sqrtf(__uint_as_float(g_dap[i]));
        float dan = sqrtf(__uint_as_float(g_dan[i]));
        int c = g_cnt[lab[i]];
        bool has_pos = (c > 1);
        bool has_neg = (c < B_N);
        float loss = dap - dan + MARGIN;
        if (has_pos && has_neg && loss > 0.f) { tot += loss; cnt++; }
    }
    ssum[tid] = tot; scnt[tid] = cnt;
    __syncthreads();
    for (int s = 512; s; s >>= 1) {
        if (tid < s) { ssum[tid] += ssum[tid + s]; scnt[tid] += scnt[tid + s]; }
        __syncthreads();
    }
    if (tid == 0) out[0] = (scnt[0] > 0) ? ssum[0] / (float)scnt[0] : 0.0f;
}

// ---------------------------------------------------------------------------
extern "C" void kernel_launch(void* const* d_in, const int* in_sizes, int n_in,
                              void* d_out, int out_size) {
    const float* emb = (const float*)d_in[0];
    const int*   lab = (const int*)d_in[1];
    float*       out = (float*)d_out;

    cudaFuncSetAttribute(tile_kernel, cudaFuncAttributeMaxDynamicSharedMemorySize,
                         SMEM_BYTES);

    zero_kernel<<<(B_N + 255) / 256, 256>>>();
    prep_kernel<<<(B_N * 32) / 256, 256>>>(emb, lab);
    dim3 grid(B_N / TILE, B_N / TILE);
    tile_kernel<<<grid, 256, SMEM_BYTES>>>(lab);
    final_kernel<<<1, 1024>>>(lab, out);
}

// round 15
// speedup vs baseline: 8.4640x; 1.4934x over previous
#include <cuda_runtime.h>
#include <cuda_bf16.h>
#include <cstdint>

#define B_N 8192
#define D_K 256
#define NCLS 64
#define MARGIN 0.5f
#define TILE 128
#define NB 64                       // B_N / TILE
#define NTILES (NB * (NB + 1) / 2)  // 2080 upper-triangular tiles
#define SCALE40 1099511627776.0     // 2^40 fixed-point scale

// Scratch (allocations are forbidden) — re-initialized every launch.
__device__ unsigned int g_dap[B_N];            // hardest positive d^2, float bits
__device__ unsigned int g_dan[B_N];            // closest  negative d^2, float bits
__device__ int          g_cnt[NCLS];
__device__ float        g_sq[B_N];
__device__ __nv_bfloat16 g_xbf[B_N * D_K];     // bf16 copy of embeddings (4 MB)
__device__ unsigned long long g_sum;           // fixed-point loss sum (2^40)
__device__ int          g_vcnt;                // valid count

// SMEM layout (bytes). Padded row stride 528 B -> conflict-free ldmatrix/STS.
#define A_STRIDE 528
#define SM_A     0
#define SM_B     67584
#define SM_LABC  135168
#define SM_SQC   135680
#define SM_LABR  136192
#define SM_SQR   136704
#define SM_MAXR  137216
#define SM_MINR  137728
#define SM_MAXC  138240
#define SM_MINC  138752
#define SMEM_BYTES 139264

__device__ __forceinline__ uint32_t smem_u32(const void* p) {
    uint32_t a;
    asm("{ .reg .u64 t; cvta.to.shared.u64 t, %1; cvt.u32.u64 %0, t; }"
        : "=r"(a) : "l"(p));
    return a;
}
__device__ __forceinline__ uint32_t pack_bf16x2(float lo, float hi) {
    __nv_bfloat162 h = __floats2bfloat162_rn(lo, hi);
    return *(uint32_t*)&h;
}

// ---------------------------------------------------------------------------
__global__ void zero_kernel() {
    int i = blockIdx.x * blockDim.x + threadIdx.x;
    if (i < B_N) { g_dap[i] = 0u; g_dan[i] = 0x7F7FFFFFu; }
    if (i < NCLS) g_cnt[i] = 0;
    if (i == 0) { g_sum = 0ull; g_vcnt = 0; }
}

// Row norms + class counts + bf16 conversion. One warp per row.
__global__ void prep_kernel(const float* __restrict__ x, const int* __restrict__ lab) {
    int gtid = blockIdx.x * blockDim.x + threadIdx.x;
    int warp = gtid >> 5;
    int lane = threadIdx.x & 31;
    if (warp < B_N) {
        const float4* xr = (const float4*)(x + (size_t)warp * D_K);
        float s = 0.f;
#pragma unroll
        for (int t = 0; t < 2; t++) {
            float4 v = xr[lane + 32 * t];
            s += v.x * v.x + v.y * v.y + v.z * v.z + v.w * v.w;
            *(uint2*)(g_xbf + (size_t)warp * D_K + (lane + 32 * t) * 4) =
                make_uint2(pack_bf16x2(v.x, v.y), pack_bf16x2(v.z, v.w));
        }
#pragma unroll
        for (int o = 16; o; o >>= 1) s += __shfl_xor_sync(0xffffffffu, s, o);
        if (lane == 0) g_sq[warp] = s;
    }
    if (gtid < B_N) atomicAdd(&g_cnt[lab[gtid]], 1);
}

// ---------------------------------------------------------------------------
// Upper-triangular 128x128 Gram tile (bf16 mma.sync) + two-sided mining:
// rows of block-I (row stats) and rows of block-J (via the transpose, column
// stats). Diagonal tiles mine rows only (symmetric duplicate).
__global__ void __launch_bounds__(256, 1)
tile_kernel(const int* __restrict__ lab) {
    extern __shared__ char smem[];
    const uint32_t sb = smem_u32(smem);
    const int tid  = threadIdx.x;
    const int wid  = tid >> 5;
    const int lane = tid & 31;

    // Decode upper-triangular tile index -> (by, bx), bx >= by.
    int rem = blockIdx.x, by = 0;
    while (rem >= NB - by) { rem -= NB - by; by++; }
    const int bx = by + rem;
    const int rowBase = by * TILE;
    const int colBase = bx * TILE;
    const bool offdiag = (bx != by);

    if (tid < TILE) {
        ((int*)(smem + SM_LABC))[tid]  = lab[colBase + tid];
        ((float*)(smem + SM_SQC))[tid] = g_sq[colBase + tid];
        ((int*)(smem + SM_LABR))[tid]  = lab[rowBase + tid];
        ((float*)(smem + SM_SQR))[tid] = g_sq[rowBase + tid];
        ((uint32_t*)(smem + SM_MAXR))[tid] = 0u;
        ((uint32_t*)(smem + SM_MINR))[tid] = 0x7F7FFFFFu;
        ((uint32_t*)(smem + SM_MAXC))[tid] = 0u;
        ((uint32_t*)(smem + SM_MINC))[tid] = 0x7F7FFFFFu;
    }

    // Stage A and B tiles (128 x 256 bf16 each). 4096 uint4 each, 16/thread.
#pragma unroll
    for (int it = 0; it < 16; it++) {
        int idx = tid + it * 256;
        int r = idx >> 5, q = idx & 31;
        uint4 va = *(const uint4*)(g_xbf + (size_t)(rowBase + r) * D_K + q * 8);
        *(uint4*)(smem + SM_A + r * A_STRIDE + q * 16) = va;
        uint4 vb = *(const uint4*)(g_xbf + (size_t)(colBase + r) * D_K + q * 8);
        *(uint4*)(smem + SM_B + r * A_STRIDE + q * 16) = vb;
    }
    __syncthreads();

    const int wm = (wid & 1) * 64;    // warp M offset
    const int wn = (wid >> 1) * 32;   // warp N offset

    float acc[4][4][4];
#pragma unroll
    for (int mf = 0; mf < 4; mf++)
#pragma unroll
        for (int nf = 0; nf < 4; nf++)
#pragma unroll
            for (int e = 0; e < 4; e++) acc[mf][nf][e] = 0.f;

#pragma unroll 4
    for (int ks = 0; ks < 16; ks++) {
        uint32_t a[4][4], b[4][2];
#pragma unroll
        for (int mf = 0; mf < 4; mf++) {
            uint32_t addr = sb + SM_A + (wm + mf * 16 + (lane & 15)) * A_STRIDE
                          + ks * 32 + (lane >> 4) * 16;
            asm volatile("ldmatrix.sync.aligned.m8n8.x4.shared.b16 "
                         "{%0,%1,%2,%3}, [%4];"
                         : "=r"(a[mf][0]), "=r"(a[mf][1]),
                           "=r"(a[mf][2]), "=r"(a[mf][3]) : "r"(addr));
        }
#pragma unroll
        for (int nf = 0; nf < 4; nf++) {
            uint32_t addr = sb + SM_B + (wn + nf * 8 + (lane & 7)) * A_STRIDE
                          + ks * 32 + ((lane >> 3) & 1) * 16;
            asm volatile("ldmatrix.sync.aligned.m8n8.x2.shared.b16 "
                         "{%0,%1}, [%2];"
                         : "=r"(b[nf][0]), "=r"(b[nf][1]) : "r"(addr));
        }
#pragma unroll
        for (int mf = 0; mf < 4; mf++)
#pragma unroll
            for (int nf = 0; nf < 4; nf++)
                asm volatile(
                    "mma.sync.aligned.m16n8k16.row.col.f32.bf16.bf16.f32 "
                    "{%0,%1,%2,%3}, {%4,%5,%6,%7}, {%8,%9}, {%0,%1,%2,%3};"
                    : "+f"(acc[mf][nf][0]), "+f"(acc[mf][nf][1]),
                      "+f"(acc[mf][nf][2]), "+f"(acc[mf][nf][3])
                    : "r"(a[mf][0]), "r"(a[mf][1]), "r"(a[mf][2]), "r"(a[mf][3]),
                      "r"(b[nf][0]), "r"(b[nf][1]));
    }

    const int*   labC = (const int*)(smem + SM_LABC);
    const float* sqC  = (const float*)(smem + SM_SQC);
    const int*   labR = (const int*)(smem + SM_LABR);
    const float* sqR  = (const float*)(smem + SM_SQR);
    uint32_t* smaxR = (uint32_t*)(smem + SM_MAXR);
    uint32_t* sminR = (uint32_t*)(smem + SM_MINR);
    uint32_t* smaxC = (uint32_t*)(smem + SM_MAXC);
    uint32_t* sminC = (uint32_t*)(smem + SM_MINC);

    // ---- Row mining: fragment rows r = wm+mf*16+(lane>>2)+half*8.
#pragma unroll
    for (int mf = 0; mf < 4; mf++) {
#pragma unroll
        for (int half = 0; half < 2; half++) {
            int r = wm + mf * 16 + (lane >> 2) + half * 8;
            int grow = rowBase + r;
            int rl = labR[r];
            float rsq = sqR[r];
            float pmax = -1.0f, nmin = 1e30f;
#pragma unroll
            for (int nf = 0; nf < 4; nf++)
#pragma unroll
                for (int e = 0; e < 2; e++) {
                    int c = wn + nf * 8 + (lane & 3) * 2 + e;
                    float dot = acc[mf][nf][half * 2 + e];
                    float d2 = fmaxf(rsq + sqC[c] - 2.0f * dot, 0.0f);
                    if (rl == labC[c]) {
                        if (colBase + c != grow) pmax = fmaxf(pmax, d2);
                    } else {
                        nmin = fminf(nmin, d2);
                    }
                }
            if (pmax >= 0.0f) atomicMax(&smaxR[r], __float_as_uint(pmax));
            if (nmin < 1e29f) atomicMin(&sminR[r], __float_as_uint(nmin));
        }
    }

    // ---- Column mining (off-diagonal only): dist(j,i) = dist(i,j).
    if (offdiag) {
#pragma unroll
        for (int nf = 0; nf < 4; nf++) {
#pragma unroll
            for (int e = 0; e < 2; e++) {
                int c = wn + nf * 8 + (lane & 3) * 2 + e;
                int cl = labC[c];
                float csq = sqC[c];
                float pmax = -1.0f, nmin = 1e30f;
#pragma unroll
                for (int mf = 0; mf < 4; mf++)
#pragma unroll
                    for (int half = 0; half < 2; half++) {
                        int r = wm + mf * 16 + (lane >> 2) + half * 8;
                        float dot = acc[mf][nf][half * 2 + e];
                        float d2 = fmaxf(csq + sqR[r] - 2.0f * dot, 0.0f);
                        if (cl == labR[r]) {
                            pmax = fmaxf(pmax, d2);   // bx>by: never self-pair
                        } else {
                            nmin = fminf(nmin, d2);
                        }
                    }
                if (pmax >= 0.0f) atomicMax(&smaxC[c], __float_as_uint(pmax));
                if (nmin < 1e29f) atomicMin(&sminC[c], __float_as_uint(nmin));
            }
        }
    }
    __syncthreads();

    if (tid < TILE) {
        if (smaxR[tid] != 0u)
            atomicMax(&g_dap[rowBase + tid], smaxR[tid]);
        if (sminR[tid] != 0x7F7FFFFFu)
            atomicMin(&g_dan[rowBase + tid], sminR[tid]);
        if (offdiag) {
            if (smaxC[tid] != 0u)
                atomicMax(&g_dap[colBase + tid], smaxC[tid]);
            if (sminC[tid] != 0x7F7FFFFFu)
                atomicMin(&g_dan[colBase + tid], sminC[tid]);
        }
    }
}

// ---------------------------------------------------------------------------
// Parallel valid-loss sum: fixed-point u64 atomics (order-independent).
__global__ void final_sum_kernel(const int* __restrict__ lab) {
    __shared__ unsigned long long bsum[256];
    __shared__ int bcnt[256];
    int tid = threadIdx.x;
    int i = blockIdx.x * 256 + tid;

    unsigned long long fx = 0ull;
    int v = 0;
    if (i < B_N) {
        float dap = sqrtf(__uint_as_float(g_dap[i]));
        float dan = sqrtf(__uint_as_float(g_dan[i]));
        int c = g_cnt[lab[i]];
        float loss = dap - dan + MARGIN;
        if (c > 1 && c < B_N && loss > 0.f) {
            fx = (unsigned long long)((double)loss * SCALE40);
            v = 1;
        }
    }
    bsum[tid] = fx; bcnt[tid] = v;
    __syncthreads();
    for (int s = 128; s; s >>= 1) {
        if (tid < s) { bsum[tid] += bsum[tid + s]; bcnt[tid] += bcnt[tid + s]; }
        __syncthreads();
    }
    if (tid == 0) {
        if (bsum[0]) atomicAdd(&g_sum, bsum[0]);
        if (bcnt[0]) atomicAdd(&g_vcnt, bcnt[0]);
    }
}

__global__ void final_out_kernel(float* __restrict__ out) {
    int cnt = g_vcnt;
    out[0] = (cnt > 0) ? (float)((double)g_sum / SCALE40 / (double)cnt) : 0.0f;
}

// ---------------------------------------------------------------------------
extern "C" void kernel_launch(void* const* d_in, const int* in_sizes, int n_in,
                              void* d_out, int out_size) {
    const float* emb = (const float*)d_in[0];
    const int*   lab = (const int*)d_in[1];
    float*       out = (float*)d_out;

    cudaFuncSetAttribute(tile_kernel, cudaFuncAttributeMaxDynamicSharedMemorySize,
                         SMEM_BYTES);

    zero_kernel<<<(B_N + 255) / 256, 256>>>();
    prep_kernel<<<(B_N * 32) / 256, 256>>>(emb, lab);
    tile_kernel<<<NTILES, 256, SMEM_BYTES>>>(lab);
    final_sum_kernel<<<B_N / 256, 256>>>(lab);
    final_out_kernel<<<1, 1>>>(out);
}

// round 17
// speedup vs baseline: 10.8750x; 1.2849x over previous
#include <cuda_runtime.h>
#include <cuda_bf16.h>
#include <cstdint>

#define B_N 8192
#define D_K 256
#define NCLS 64
#define MARGIN 0.5f
#define TILE 128
#define NB 64                       // B_N / TILE
#define NTILES (NB * (NB + 1) / 2)  // 2080 upper-triangular tiles
#define SCALE40 1099511627776.0     // 2^40 fixed-point scale

#define KC 64                       // K-chunk (bf16 elems)
#define NCHUNK 4
#define CH_STRIDE 144               // bytes per row in a staged chunk (128+16)
#define CH_BYTES (TILE * CH_STRIDE) // 18432

// Scratch (allocations are forbidden) — re-initialized every launch.
__device__ unsigned int g_dap[B_N];            // hardest positive d^2, float bits
__device__ unsigned int g_dan[B_N];            // closest  negative d^2, float bits
__device__ int          g_cnt[NCLS];
__device__ float        g_sq[B_N];
__device__ __nv_bfloat16 g_xbf[B_N * D_K];     // bf16 copy of embeddings (4 MB)
__device__ unsigned long long g_sum;           // fixed-point loss sum (2^40)
__device__ int          g_vcnt;                // valid count
__device__ unsigned int g_done;                // last-block ticket

// SMEM layout (bytes): 2 x (A chunk + B chunk) double buffer + metadata.
#define SM_A0    0
#define SM_B0    18432
#define SM_A1    36864
#define SM_B1    55296
#define SM_LABC  73728
#define SM_SQC   74240
#define SM_LABR  74752
#define SM_SQR   75264
#define SM_MAXR  75776
#define SM_MINR  76288
#define SM_MAXC  76800
#define SM_MINC  77312
#define SMEM_BYTES 77824

__device__ __forceinline__ uint32_t smem_u32(const void* p) {
    uint32_t a;
    asm("{ .reg .u64 t; cvta.to.shared.u64 t, %1; cvt.u32.u64 %0, t; }"
        : "=r"(a) : "l"(p));
    return a;
}
__device__ __forceinline__ uint32_t pack_bf16x2(float lo, float hi) {
    __nv_bfloat162 h = __floats2bfloat162_rn(lo, hi);
    return *(uint32_t*)&h;
}
__device__ __forceinline__ void cp16(uint32_t saddr, const void* gptr) {
    asm volatile("cp.async.cg.shared.global [%0], [%1], 16;"
                 :: "r"(saddr), "l"(gptr));
}
#define CP_COMMIT() asm volatile("cp.async.commit_group;" ::: "memory")
#define CP_WAIT(n)  asm volatile("cp.async.wait_group %0;" :: "n"(n) : "memory")

// ---------------------------------------------------------------------------
__global__ void zero_kernel() {
    int i = blockIdx.x * blockDim.x + threadIdx.x;
    if (i < B_N) { g_dap[i] = 0u; g_dan[i] = 0x7F7FFFFFu; }
    if (i < NCLS) g_cnt[i] = 0;
    if (i == 0) { g_sum = 0ull; g_vcnt = 0; g_done = 0u; }
}

// Row norms + class counts + bf16 conversion. One warp per row.
__global__ void prep_kernel(const float* __restrict__ x, const int* __restrict__ lab) {
    int gtid = blockIdx.x * blockDim.x + threadIdx.x;
    int warp = gtid >> 5;
    int lane = threadIdx.x & 31;
    if (warp < B_N) {
        const float4* xr = (const float4*)(x + (size_t)warp * D_K);
        float s = 0.f;
#pragma unroll
        for (int t = 0; t < 2; t++) {
            float4 v = xr[lane + 32 * t];
            s += v.x * v.x + v.y * v.y + v.z * v.z + v.w * v.w;
            *(uint2*)(g_xbf + (size_t)warp * D_K + (lane + 32 * t) * 4) =
                make_uint2(pack_bf16x2(v.x, v.y), pack_bf16x2(v.z, v.w));
        }
#pragma unroll
        for (int o = 16; o; o >>= 1) s += __shfl_xor_sync(0xffffffffu, s, o);
        if (lane == 0) g_sq[warp] = s;
    }
    if (gtid < B_N) atomicAdd(&g_cnt[lab[gtid]], 1);
}

// ---------------------------------------------------------------------------
// Upper-triangular 128x128 Gram tile, cp.async double-buffered over 4 K-chunks,
// bf16 mma.sync, two-sided (row+column) mining on d^2.
__global__ void __launch_bounds__(256, 2)
tile_kernel(const int* __restrict__ lab) {
    extern __shared__ char smem[];
    const uint32_t sb = smem_u32(smem);
    const int tid  = threadIdx.x;
    const int wid  = tid >> 5;
    const int lane = tid & 31;

    // Decode upper-triangular tile index -> (by, bx), bx >= by.
    int rem = blockIdx.x, by = 0;
    while (rem >= NB - by) { rem -= NB - by; by++; }
    const int bx = by + rem;
    const int rowBase = by * TILE;
    const int colBase = bx * TILE;
    const bool offdiag = (bx != by);

    if (tid < TILE) {
        ((int*)(smem + SM_LABC))[tid]  = lab[colBase + tid];
        ((float*)(smem + SM_SQC))[tid] = g_sq[colBase + tid];
        ((int*)(smem + SM_LABR))[tid]  = lab[rowBase + tid];
        ((float*)(smem + SM_SQR))[tid] = g_sq[rowBase + tid];
        ((uint32_t*)(smem + SM_MAXR))[tid] = 0u;
        ((uint32_t*)(smem + SM_MINR))[tid] = 0x7F7FFFFFu;
        ((uint32_t*)(smem + SM_MAXC))[tid] = 0u;
        ((uint32_t*)(smem + SM_MINC))[tid] = 0x7F7FFFFFu;
    }

    const uint32_t aoff[2] = {SM_A0, SM_A1};
    const uint32_t boff[2] = {SM_B0, SM_B1};

    // Stage one K-chunk (A and B, 128x64 bf16 each) via cp.async.
    // 1024 16B ops per operand; 4 per thread per operand.
    auto load_chunk = [&](int c, uint32_t ao, uint32_t bo) {
        const int kc = c * KC;
#pragma unroll
        for (int it = 0; it < 4; it++) {
            int idx = tid + it * 256;
            int r = idx >> 3, q = idx & 7;       // q: 16B chunk within 128B row
            cp16(sb + ao + r * CH_STRIDE + q * 16,
                 g_xbf + (size_t)(rowBase + r) * D_K + kc + q * 8);
            cp16(sb + bo + r * CH_STRIDE + q * 16,
                 g_xbf + (size_t)(colBase + r) * D_K + kc + q * 8);
        }
        CP_COMMIT();
    };

    load_chunk(0, SM_A0, SM_B0);

    const int wm = (wid & 1) * 64;    // warp M offset
    const int wn = (wid >> 1) * 32;   // warp N offset

    float acc[4][4][4];
#pragma unroll
    for (int mf = 0; mf < 4; mf++)
#pragma unroll
        for (int nf = 0; nf < 4; nf++)
#pragma unroll
            for (int e = 0; e < 4; e++) acc[mf][nf][e] = 0.f;

#pragma unroll 1
    for (int c = 0; c < NCHUNK; c++) {
        if (c + 1 < NCHUNK)
            load_chunk(c + 1, aoff[(c + 1) & 1], boff[(c + 1) & 1]);
        if (c + 1 < NCHUNK) { CP_WAIT(1); } else { CP_WAIT(0); }
        __syncthreads();

        const uint32_t ab = sb + aoff[c & 1];
        const uint32_t bb = sb + boff[c & 1];
#pragma unroll
        for (int ks = 0; ks < 4; ks++) {          // 4 x K=16 within chunk
            uint32_t a[4][4], b[4][2];
#pragma unroll
            for (int mf = 0; mf < 4; mf++) {
                uint32_t addr = ab + (wm + mf * 16 + (lane & 15)) * CH_STRIDE
                              + ks * 32 + (lane >> 4) * 16;
                asm volatile("ldmatrix.sync.aligned.m8n8.x4.shared.b16 "
                             "{%0,%1,%2,%3}, [%4];"
                             : "=r"(a[mf][0]), "=r"(a[mf][1]),
                               "=r"(a[mf][2]), "=r"(a[mf][3]) : "r"(addr));
            }
#pragma unroll
            for (int nf = 0; nf < 4; nf++) {
                uint32_t addr = bb + (wn + nf * 8 + (lane & 7)) * CH_STRIDE
                              + ks * 32 + ((lane >> 3) & 1) * 16;
                asm volatile("ldmatrix.sync.aligned.m8n8.x2.shared.b16 "
                             "{%0,%1}, [%2];"
                             : "=r"(b[nf][0]), "=r"(b[nf][1]) : "r"(addr));
            }
#pragma unroll
            for (int mf = 0; mf < 4; mf++)
#pragma unroll
                for (int nf = 0; nf < 4; nf++)
                    asm volatile(
                        "mma.sync.aligned.m16n8k16.row.col.f32.bf16.bf16.f32 "
                        "{%0,%1,%2,%3}, {%4,%5,%6,%7}, {%8,%9}, {%0,%1,%2,%3};"
                        : "+f"(acc[mf][nf][0]), "+f"(acc[mf][nf][1]),
                          "+f"(acc[mf][nf][2]), "+f"(acc[mf][nf][3])
                        : "r"(a[mf][0]), "r"(a[mf][1]), "r"(a[mf][2]), "r"(a[mf][3]),
                          "r"(b[nf][0]), "r"(b[nf][1]));
        }
        __syncthreads();   // chunk c consumed; its buffer may be overwritten
    }

    const int*   labC = (const int*)(smem + SM_LABC);
    const float* sqC  = (const float*)(smem + SM_SQC);
    const int*   labR = (const int*)(smem + SM_LABR);
    const float* sqR  = (const float*)(smem + SM_SQR);
    uint32_t* smaxR = (uint32_t*)(smem + SM_MAXR);
    uint32_t* sminR = (uint32_t*)(smem + SM_MINR);
    uint32_t* smaxC = (uint32_t*)(smem + SM_MAXC);
    uint32_t* sminC = (uint32_t*)(smem + SM_MINC);

    // ---- Row mining: fragment rows r = wm+mf*16+(lane>>2)+half*8.
#pragma unroll
    for (int mf = 0; mf < 4; mf++) {
#pragma unroll
        for (int half = 0; half < 2; half++) {
            int r = wm + mf * 16 + (lane >> 2) + half * 8;
            int grow = rowBase + r;
            int rl = labR[r];
            float rsq = sqR[r];
            float pmax = -1.0f, nmin = 1e30f;
#pragma unroll
            for (int nf = 0; nf < 4; nf++)
#pragma unroll
                for (int e = 0; e < 2; e++) {
                    int c = wn + nf * 8 + (lane & 3) * 2 + e;
                    float dot = acc[mf][nf][half * 2 + e];
                    float d2 = fmaxf(rsq + sqC[c] - 2.0f * dot, 0.0f);
                    if (rl == labC[c]) {
                        if (colBase + c != grow) pmax = fmaxf(pmax, d2);
                    } else {
                        nmin = fminf(nmin, d2);
                    }
                }
            if (pmax >= 0.0f) atomicMax(&smaxR[r], __float_as_uint(pmax));
            if (nmin < 1e29f) atomicMin(&sminR[r], __float_as_uint(nmin));
        }
    }

    // ---- Column mining (off-diagonal only): dist(j,i) = dist(i,j).
    if (offdiag) {
#pragma unroll
        for (int nf = 0; nf < 4; nf++) {
#pragma unroll
            for (int e = 0; e < 2; e++) {
                int c = wn + nf * 8 + (lane & 3) * 2 + e;
                int cl = labC[c];
                float csq = sqC[c];
                float pmax = -1.0f, nmin = 1e30f;
#pragma unroll
                for (int mf = 0; mf < 4; mf++)
#pragma unroll
                    for (int half = 0; half < 2; half++) {
                        int r = wm + mf * 16 + (lane >> 2) + half * 8;
                        float dot = acc[mf][nf][half * 2 + e];
                        float d2 = fmaxf(csq + sqR[r] - 2.0f * dot, 0.0f);
                        if (cl == labR[r]) {
                            pmax = fmaxf(pmax, d2);   // bx>by: never self-pair
                        } else {
                            nmin = fminf(nmin, d2);
                        }
                    }
                if (pmax >= 0.0f) atomicMax(&smaxC[c], __float_as_uint(pmax));
                if (nmin < 1e29f) atomicMin(&sminC[c], __float_as_uint(nmin));
            }
        }
    }
    __syncthreads();

    if (tid < TILE) {
        if (smaxR[tid] != 0u)
            atomicMax(&g_dap[rowBase + tid], smaxR[tid]);
        if (sminR[tid] != 0x7F7FFFFFu)
            atomicMin(&g_dan[rowBase + tid], sminR[tid]);
        if (offdiag) {
            if (smaxC[tid] != 0u)
                atomicMax(&g_dap[colBase + tid], smaxC[tid]);
            if (sminC[tid] != 0x7F7FFFFFu)
                atomicMin(&g_dan[colBase + tid], sminC[tid]);
        }
    }
}

// ---------------------------------------------------------------------------
// Parallel valid-loss sum (fixed-point u64, order-independent) + last-block
// writes the final mean.
__global__ void final_sum_kernel(const int* __restrict__ lab,
                                 float* __restrict__ out) {
    __shared__ unsigned long long bsum[256];
    __shared__ int bcnt[256];
    int tid = threadIdx.x;
    int i = blockIdx.x * 256 + tid;

    unsigned long long fx = 0ull;
    int v = 0;
    if (i < B_N) {
        float dap = sqrtf(__uint_as_float(g_dap[i]));
        float dan = sqrtf(__uint_as_float(g_dan[i]));
        int c = g_cnt[lab[i]];
        float loss = dap - dan + MARGIN;
        if (c > 1 && c < B_N && loss > 0.f) {
            fx = (unsigned long long)((double)loss * SCALE40);
            v = 1;
        }
    }
    bsum[tid] = fx; bcnt[tid] = v;
    __syncthreads();
    for (int s = 128; s; s >>= 1) {
        if (tid < s) { bsum[tid] += bsum[tid + s]; bcnt[tid] += bcnt[tid + s]; }
        __syncthreads();
    }
    if (tid == 0) {
        atomicAdd(&g_sum, bsum[0]);
        atomicAdd(&g_vcnt, bcnt[0]);
        __threadfence();
        unsigned int t = atomicAdd(&g_done, 1u);
        if (t == gridDim.x - 1) {               // last block: publish result
            int cnt = g_vcnt;
            out[0] = (cnt > 0)
                   ? (float)((double)g_sum / SCALE40 / (double)cnt) : 0.0f;
        }
    }
}

// ---------------------------------------------------------------------------
extern "C" void kernel_launch(void* const* d_in, const int* in_sizes, int n_in,
                              void* d_out, int out_size) {
    const float* emb = (const float*)d_in[0];
    const int*   lab = (const int*)d_in[1];
    float*       out = (float*)d_out;

    cudaFuncSetAttribute(tile_kernel, cudaFuncAttributeMaxDynamicSharedMemorySize,
                         SMEM_BYTES);

    zero_kernel<<<(B_N + 255) / 256, 256>>>();
    prep_kernel<<<(B_N * 32) / 256, 256>>>(emb, lab);
    tile_kernel<<<NTILES, 256, SMEM_BYTES>>>(lab);
    final_sum_kernel<<<B_N / 256, 256>>>(lab, out);
}